// round 13
// baseline (speedup 1.0000x reference)
#include <cuda_runtime.h>

// Shapes fixed by the problem: B=2, S=8, N=2048, D=3
#define NPTS    2048
#define BS_     16             // B*S
#define THREADS 256            // 8 warps
#define NWARP   8
#define QPB     256            // queries per block (8 per lane)
#define CHUNKS  (NPTS / QPB)   // 8
#define NBLK    (CHUNKS * BS_ * 2)      // 256
#define SLOTS_PER_WARP (NPTS / 2 / NWARP)  // 128 float4 slots per warp
#define SEG_SLOTS 32                    // 32 slots = 64 targets per segment
#define NSEG      (SLOTS_PER_WARP / SEG_SLOTS)  // 4 segments per warp-eighth

typedef unsigned long long ull;

__device__ float g_part[NBLK];
__device__ float g_cent[NBLK][3];
__device__ int   g_count;              // zero-init; self-resets each run

__device__ __forceinline__ float smooth_l1(float d) {
    float a = fabsf(d);
    return (a < 1.0f) ? 0.5f * a * a : a - 0.5f;
}

// 3-input max -> single FMNMX3 (sm_90+).
__device__ __forceinline__ float fmax3(float a, float b, float c) {
    float d;
    asm("max.f32 %0, %1, %2, %3;" : "=f"(d) : "f"(a), "f"(b), "f"(c));
    return d;
}

// Packed 2-point score: s = px*x + py*y + pz*z + w (w = -0.5*|t|^2).
__device__ __forceinline__ void score2(
    ull px2, ull py2, ull pz2,
    ull x2, ull y2, ull z2, ull w2,
    float& s0, float& s1)
{
    asm("{\n\t"
        ".reg .b64 t;\n\t"
        "fma.rn.f32x2 t, %4, %7, %8;\n\t"   // pz*z + w
        "fma.rn.f32x2 t, %3, %6, t;\n\t"    // + py*y
        "fma.rn.f32x2 t, %2, %5, t;\n\t"    // + px*x
        "mov.b64 {%0, %1}, t;\n\t"
        "}"
        : "=f"(s0), "=f"(s1)
        : "l"(px2), "l"(py2), "l"(pz2), "l"(x2), "l"(y2), "l"(z2), "l"(w2));
}

__device__ __forceinline__ ull pack2(float v) {
    float2 t = make_float2(v, v);
    return *reinterpret_cast<ull*>(&t);
}

// Mantissa-packed keys.
__device__ __forceinline__ float key11(float s, int j) {   // 11-bit target idx
    return __int_as_float((__float_as_int(s) & 0xFFFFF800) | j);
}
__device__ __forceinline__ float key5(float s, int ws) {   // 5-bit segment idx
    return __int_as_float((__float_as_int(s) & 0xFFFFFFE0) | ws);
}

// Pass-1 body: one query against 4 packed slots (8 targets), single
// accumulator, FMNMX3 folds both packed halves per score2.
#define EVAL_Q(QX, QY, QZ, M)                                             \
    do {                                                                   \
        float u0, u1;                                                      \
        score2(QX, QY, QZ, xy0.x, xy0.y, zw0.x, zw0.y, u0, u1);           \
        M = fmax3(M, u0, u1);                                              \
        score2(QX, QY, QZ, xy1.x, xy1.y, zw1.x, zw1.y, u0, u1);           \
        M = fmax3(M, u0, u1);                                              \
        score2(QX, QY, QZ, xy2.x, xy2.y, zw2.x, zw2.y, u0, u1);           \
        M = fmax3(M, u0, u1);                                              \
        score2(QX, QY, QZ, xy3.x, xy3.y, zw3.x, zw3.y, u0, u1);           \
        M = fmax3(M, u0, u1);                                              \
    } while (0)

// blockIdx.x: chunk (0..7), blockIdx.y: bs, blockIdx.z: dir (0: X->T, 1: T->X)
__global__ __launch_bounds__(THREADS, 2) void chamfer_kernel(
    const float* __restrict__ X,
    const float* __restrict__ T,
    const float* __restrict__ W,
    float* __restrict__ out)
{
    __shared__ float4 sXY[NPTS / 2];       // (x0,x1,y0,y1)   16 KB
    __shared__ float4 sZW[NPTS / 2];       // (z0,z1,w0,w1)   16 KB
    __shared__ float  sKey[NWARP * QPB];   // per-warp segment keys, 8 KB
    __shared__ float  sRed[4][NWARP];
    __shared__ bool   sLast;

    const int bs  = blockIdx.y;
    const int dir = blockIdx.z;
    const float* pred = dir ? T : X;
    const float* ref  = dir ? X : T;
    const float* refBase = ref + (size_t)bs * NPTS * 3;
    const int tid  = threadIdx.x;
    const int lane = tid & 31;
    const int w    = tid >> 5;         // warp id -> target eighth

    // Load full ref set into smem as packed pairs.
    for (int t = tid; t < NPTS / 2; t += THREADS) {
        const float2* qp = reinterpret_cast<const float2*>(refBase + 6 * t);
        float2 a = qp[0], b = qp[1], c = qp[2];
        float x0 = a.x, y0 = a.y, z0 = b.x;
        float x1 = b.y, y1 = c.x, z1 = c.y;
        float w0 = -0.5f * (x0 * x0 + y0 * y0 + z0 * z0);
        float w1 = -0.5f * (x1 * x1 + y1 * y1 + z1 * z1);
        sXY[t] = make_float4(x0, x1, y0, y1);
        sZW[t] = make_float4(z0, z1, w0, w1);
    }
    __syncthreads();

    // My eight query points: qBase + {0..7} (96 contiguous bytes).
    const int qBase = blockIdx.x * QPB + 8 * lane;
    const float4* qp = reinterpret_cast<const float4*>(
        pred + ((size_t)bs * NPTS + qBase) * 3);
    float4 f0 = qp[0], f1 = qp[1], f2 = qp[2];
    float4 f3 = qp[3], f4 = qp[4], f5 = qp[5];
    const ull Ax = pack2(f0.x), Ay = pack2(f0.y), Az = pack2(f0.z);
    const ull Bx = pack2(f0.w), By = pack2(f1.x), Bz = pack2(f1.y);
    const ull Cx = pack2(f1.z), Cy = pack2(f1.w), Cz = pack2(f2.x);
    const ull Dx = pack2(f2.y), Dy = pack2(f2.z), Dz = pack2(f2.w);
    const ull Ex = pack2(f3.x), Ey = pack2(f3.y), Ez = pack2(f3.z);
    const ull Fx = pack2(f3.w), Fy = pack2(f4.x), Fz = pack2(f4.y);
    const ull Gx = pack2(f4.z), Gy = pack2(f4.w), Gz = pack2(f5.x);
    const ull Hx = pack2(f5.y), Hy = pack2(f5.z), Hz = pack2(f5.w);

    // ── Pass 1: segment maxima over my eighth of the targets. ──
    float gA = -1e30f, gB = -1e30f, gC = -1e30f, gD = -1e30f;
    float gE = -1e30f, gF = -1e30f, gG = -1e30f, gH = -1e30f;
    const int sBeg = w * SLOTS_PER_WARP;

    for (int seg = 0; seg < NSEG; seg++) {
        float mA = -1e30f, mB = -1e30f, mC = -1e30f, mD = -1e30f;
        float mE = -1e30f, mF = -1e30f, mG = -1e30f, mH = -1e30f;
        const int segSlot = sBeg + seg * SEG_SLOTS;

        #pragma unroll
        for (int g = 0; g < SEG_SLOTS / 4; g++) {
            const int s = segSlot + g * 4;
            ulonglong2 xy0 = *reinterpret_cast<const ulonglong2*>(&sXY[s + 0]);
            ulonglong2 zw0 = *reinterpret_cast<const ulonglong2*>(&sZW[s + 0]);
            ulonglong2 xy1 = *reinterpret_cast<const ulonglong2*>(&sXY[s + 1]);
            ulonglong2 zw1 = *reinterpret_cast<const ulonglong2*>(&sZW[s + 1]);
            ulonglong2 xy2 = *reinterpret_cast<const ulonglong2*>(&sXY[s + 2]);
            ulonglong2 zw2 = *reinterpret_cast<const ulonglong2*>(&sZW[s + 2]);
            ulonglong2 xy3 = *reinterpret_cast<const ulonglong2*>(&sXY[s + 3]);
            ulonglong2 zw3 = *reinterpret_cast<const ulonglong2*>(&sZW[s + 3]);

            EVAL_Q(Ax, Ay, Az, mA);
            EVAL_Q(Bx, By, Bz, mB);
            EVAL_Q(Cx, Cy, Cz, mC);
            EVAL_Q(Dx, Dy, Dz, mD);
            EVAL_Q(Ex, Ey, Ez, mE);
            EVAL_Q(Fx, Fy, Fz, mF);
            EVAL_Q(Gx, Gy, Gz, mG);
            EVAL_Q(Hx, Hy, Hz, mH);
        }
        const int ws = w * NSEG + seg;       // in [0, 32)
        gA = fmaxf(gA, key5(mA, ws));
        gB = fmaxf(gB, key5(mB, ws));
        gC = fmaxf(gC, key5(mC, ws));
        gD = fmaxf(gD, key5(mD, ws));
        gE = fmaxf(gE, key5(mE, ws));
        gF = fmaxf(gF, key5(mF, ws));
        gG = fmaxf(gG, key5(mG, ws));
        gH = fmaxf(gH, key5(mH, ws));
    }

    {
        float* dst = &sKey[w * QPB + 8 * lane];
        dst[0] = gA; dst[1] = gB; dst[2] = gC; dst[3] = gD;
        dst[4] = gE; dst[5] = gF; dst[6] = gG; dst[7] = gH;
    }
    __syncthreads();

    // ── Pass 2: thread tid = query tid; re-scan the winning 64-target segment. ──
    const int qq = blockIdx.x * QPB + tid;
    const float* pq = pred + ((size_t)bs * NPTS + qq) * 3;
    const float px = pq[0], py = pq[1], pz = pq[2];
    const ull qx2 = pack2(px), qy2 = pack2(py), qz2 = pack2(pz);

    float bestSeg = fmaxf(
        fmaxf(fmaxf(sKey[tid],           sKey[QPB + tid]),
              fmaxf(sKey[2 * QPB + tid], sKey[3 * QPB + tid])),
        fmaxf(fmaxf(sKey[4 * QPB + tid], sKey[5 * QPB + tid]),
              fmaxf(sKey[6 * QPB + tid], sKey[7 * QPB + tid])));
    const int wsWin    = __float_as_int(bestSeg) & 31;
    const int slotBase = wsWin * SEG_SLOTS;

    float kk = -1e30f;
    #pragma unroll 4
    for (int ii = 0; ii < SEG_SLOTS; ii++) {
        const int s = slotBase + ((ii + lane) & (SEG_SLOTS - 1));
        ulonglong2 xy = *reinterpret_cast<const ulonglong2*>(&sXY[s]);
        ulonglong2 zw = *reinterpret_cast<const ulonglong2*>(&sZW[s]);
        float u0, u1;
        score2(qx2, qy2, qz2, xy.x, xy.y, zw.x, zw.y, u0, u1);
        kk = fmax3(kk, key11(u0, 2 * s), key11(u1, 2 * s + 1));
    }
    const int bi   = __float_as_int(kk) & 2047;
    const int slot = bi >> 1;
    const bool odd = bi & 1;
    float4 xy = sXY[slot];
    float4 zw = sZW[slot];
    float tx = odd ? xy.y : xy.x;
    float ty = odd ? xy.w : xy.z;
    float tz = odd ? zw.y : zw.x;

    float v0 = smooth_l1(px - tx) + smooth_l1(py - ty) + smooth_l1(pz - tz);
    float v1 = px, v2 = py, v3 = pz;

    // Block reduction over all 8 warps.
    #pragma unroll
    for (int o = 16; o > 0; o >>= 1) {
        v0 += __shfl_down_sync(0xFFFFFFFFu, v0, o);
        v1 += __shfl_down_sync(0xFFFFFFFFu, v1, o);
        v2 += __shfl_down_sync(0xFFFFFFFFu, v2, o);
        v3 += __shfl_down_sync(0xFFFFFFFFu, v3, o);
    }
    if (lane == 0) {
        sRed[0][w] = v0;
        sRed[1][w] = v1;
        sRed[2][w] = v2;
        sRed[3][w] = v3;
    }
    __syncthreads();
    if (tid == 0) {
        float t0 = 0, t1 = 0, t2 = 0, t3 = 0;
        #pragma unroll
        for (int k = 0; k < NWARP; k++) {
            t0 += sRed[0][k]; t1 += sRed[1][k];
            t2 += sRed[2][k]; t3 += sRed[3][k];
        }
        const int bid = blockIdx.x + CHUNKS * (bs + BS_ * dir);
        g_part[bid] = t0 * W[bs] * (1.0f / (2.0f * (float)NPTS * 3.0f));
        g_cent[bid][0] = t1;
        g_cent[bid][1] = t2;
        g_cent[bid][2] = t3;
        __threadfence();
        sLast = (atomicAdd(&g_count, 1) == NBLK - 1);
    }
    __syncthreads();

    // ── Last block finalizes both outputs. ──
    if (sLast) {
        float s = 0.0f;
        for (int k = tid; k < NBLK; k += THREADS) s += g_part[k];

        float c = 0.0f;
        if (tid < 48) {
            const int b = tid / 3, d = tid % 3;
            float sx = 0.0f, st = 0.0f;
            #pragma unroll
            for (int ch = 0; ch < CHUNKS; ch++) {
                sx += g_cent[ch + CHUNKS * b][d];                 // dir 0 -> X
                st += g_cent[ch + CHUNKS * (b + BS_)][d];         // dir 1 -> T
            }
            c = smooth_l1((sx - st) * (1.0f / (float)NPTS));
        }

        #pragma unroll
        for (int o = 16; o > 0; o >>= 1) {
            s += __shfl_down_sync(0xFFFFFFFFu, s, o);
            c += __shfl_down_sync(0xFFFFFFFFu, c, o);
        }
        __shared__ float fRed[2][NWARP];
        if (lane == 0) { fRed[0][w] = s; fRed[1][w] = c; }
        __syncthreads();
        if (tid == 0) {
            float ts = 0, tc = 0;
            #pragma unroll
            for (int k = 0; k < NWARP; k++) { ts += fRed[0][k]; tc += fRed[1][k]; }
            out[0] = ts;
            out[1] = tc * (1.0f / 6.0f);   // / (B*3)
            g_count = 0;                   // self-reset for replay
        }
    }
}

extern "C" void kernel_launch(void* const* d_in, const int* in_sizes, int n_in,
                              void* d_out, int out_size) {
    const float* X = (const float*)d_in[0];   // [B,S,N,3]
    const float* T = (const float*)d_in[1];   // [B,S,N,3]
    const float* W = (const float*)d_in[2];   // [B,S]
    float* out = (float*)d_out;               // [2] -> (loss, lossc)

    dim3 grid(CHUNKS, BS_, 2);
    chamfer_kernel<<<grid, THREADS>>>(X, T, W, out);
}

// round 14
// speedup vs baseline: 1.0088x; 1.0088x over previous
#include <cuda_runtime.h>

// Shapes fixed by the problem: B=2, S=8, N=2048, D=3
#define NPTS    2048
#define BS_     16             // B*S
#define THREADS 256            // 8 warps
#define NWARP   8
#define QPB     128            // queries per block (4 per lane)
#define CHUNKS  (NPTS / QPB)   // 16
#define NBLK    (CHUNKS * BS_ * 2)      // 512
#define SLOTS_PER_WARP (NPTS / 2 / NWARP)  // 128 float4 slots per warp
#define SEG_SLOTS 32                    // 32 slots = 64 targets per segment
#define NSEG      (SLOTS_PER_WARP / SEG_SLOTS)  // 4 segments per warp-eighth

typedef unsigned long long ull;

__device__ float g_part[NBLK];
__device__ float g_cent[NBLK][3];
__device__ int   g_count;              // zero-init; self-resets each run

__device__ __forceinline__ float smooth_l1(float d) {
    float a = fabsf(d);
    return (a < 1.0f) ? 0.5f * a * a : a - 0.5f;
}

// 3-input max -> single FMNMX3 (sm_90+).
__device__ __forceinline__ float fmax3(float a, float b, float c) {
    float d;
    asm("max.f32 %0, %1, %2, %3;" : "=f"(d) : "f"(a), "f"(b), "f"(c));
    return d;
}

// Packed 2-point score: s = px*x + py*y + pz*z + w (w = -0.5*|t|^2).
__device__ __forceinline__ void score2(
    ull px2, ull py2, ull pz2,
    ull x2, ull y2, ull z2, ull w2,
    float& s0, float& s1)
{
    asm("{\n\t"
        ".reg .b64 t;\n\t"
        "fma.rn.f32x2 t, %4, %7, %8;\n\t"   // pz*z + w
        "fma.rn.f32x2 t, %3, %6, t;\n\t"    // + py*y
        "fma.rn.f32x2 t, %2, %5, t;\n\t"    // + px*x
        "mov.b64 {%0, %1}, t;\n\t"
        "}"
        : "=f"(s0), "=f"(s1)
        : "l"(px2), "l"(py2), "l"(pz2), "l"(x2), "l"(y2), "l"(z2), "l"(w2));
}

__device__ __forceinline__ ull pack2(float v) {
    float2 t = make_float2(v, v);
    return *reinterpret_cast<ull*>(&t);
}

// Mantissa-packed keys.
__device__ __forceinline__ float key11(float s, int j) {   // 11-bit target idx
    return __int_as_float((__float_as_int(s) & 0xFFFFF800) | j);
}
__device__ __forceinline__ float key5(float s, int ws) {   // 5-bit segment idx
    return __int_as_float((__float_as_int(s) & 0xFFFFFFE0) | ws);
}

// Pass-1 body: one query against 4 packed slots (8 targets), single
// accumulator, FMNMX3 folds both packed halves per score2.
#define EVAL_Q(QX, QY, QZ, M)                                             \
    do {                                                                   \
        float u0, u1;                                                      \
        score2(QX, QY, QZ, xy0.x, xy0.y, zw0.x, zw0.y, u0, u1);           \
        M = fmax3(M, u0, u1);                                              \
        score2(QX, QY, QZ, xy1.x, xy1.y, zw1.x, zw1.y, u0, u1);           \
        M = fmax3(M, u0, u1);                                              \
        score2(QX, QY, QZ, xy2.x, xy2.y, zw2.x, zw2.y, u0, u1);           \
        M = fmax3(M, u0, u1);                                              \
        score2(QX, QY, QZ, xy3.x, xy3.y, zw3.x, zw3.y, u0, u1);           \
        M = fmax3(M, u0, u1);                                              \
    } while (0)

// blockIdx.x: chunk (0..15), blockIdx.y: bs, blockIdx.z: dir (0: X->T, 1: T->X)
// 256 threads / 8 warps, 4 queries per lane, 3 blocks/SM -> 6 warps/SMSP.
__global__ __launch_bounds__(THREADS, 3) void chamfer_kernel(
    const float* __restrict__ X,
    const float* __restrict__ T,
    const float* __restrict__ W,
    float* __restrict__ out)
{
    __shared__ float4 sXY[NPTS / 2];       // (x0,x1,y0,y1)   16 KB
    __shared__ float4 sZW[NPTS / 2];       // (z0,z1,w0,w1)   16 KB
    __shared__ float  sKey[NWARP * QPB];   // per-warp segment keys, 4 KB
    __shared__ float  sRed[4][NWARP];
    __shared__ bool   sLast;

    const int bs  = blockIdx.y;
    const int dir = blockIdx.z;
    const float* pred = dir ? T : X;
    const float* ref  = dir ? X : T;
    const float* refBase = ref + (size_t)bs * NPTS * 3;
    const int tid  = threadIdx.x;
    const int lane = tid & 31;
    const int w    = tid >> 5;         // warp id -> target eighth

    // Load full ref set into smem as packed pairs.
    for (int t = tid; t < NPTS / 2; t += THREADS) {
        const float2* qp = reinterpret_cast<const float2*>(refBase + 6 * t);
        float2 a = qp[0], b = qp[1], c = qp[2];
        float x0 = a.x, y0 = a.y, z0 = b.x;
        float x1 = b.y, y1 = c.x, z1 = c.y;
        float w0 = -0.5f * (x0 * x0 + y0 * y0 + z0 * z0);
        float w1 = -0.5f * (x1 * x1 + y1 * y1 + z1 * z1);
        sXY[t] = make_float4(x0, x1, y0, y1);
        sZW[t] = make_float4(z0, z1, w0, w1);
    }
    __syncthreads();

    // My four query points: qBase + {0,1,2,3} (48 contiguous bytes).
    const int qBase = blockIdx.x * QPB + 4 * lane;
    const float4* qp = reinterpret_cast<const float4*>(
        pred + ((size_t)bs * NPTS + qBase) * 3);
    float4 f0 = qp[0], f1 = qp[1], f2 = qp[2];
    const ull Ax = pack2(f0.x), Ay = pack2(f0.y), Az = pack2(f0.z);
    const ull Bx = pack2(f0.w), By = pack2(f1.x), Bz = pack2(f1.y);
    const ull Cx = pack2(f1.z), Cy = pack2(f1.w), Cz = pack2(f2.x);
    const ull Dx = pack2(f2.y), Dy = pack2(f2.z), Dz = pack2(f2.w);

    // ── Pass 1: segment maxima over my eighth of the targets. ──
    float gA = -1e30f, gB = -1e30f, gC = -1e30f, gD = -1e30f;
    const int sBeg = w * SLOTS_PER_WARP;

    for (int seg = 0; seg < NSEG; seg++) {
        float mA = -1e30f, mB = -1e30f, mC = -1e30f, mD = -1e30f;
        const int segSlot = sBeg + seg * SEG_SLOTS;

        #pragma unroll
        for (int g = 0; g < SEG_SLOTS / 4; g++) {
            const int s = segSlot + g * 4;
            ulonglong2 xy0 = *reinterpret_cast<const ulonglong2*>(&sXY[s + 0]);
            ulonglong2 zw0 = *reinterpret_cast<const ulonglong2*>(&sZW[s + 0]);
            ulonglong2 xy1 = *reinterpret_cast<const ulonglong2*>(&sXY[s + 1]);
            ulonglong2 zw1 = *reinterpret_cast<const ulonglong2*>(&sZW[s + 1]);
            ulonglong2 xy2 = *reinterpret_cast<const ulonglong2*>(&sXY[s + 2]);
            ulonglong2 zw2 = *reinterpret_cast<const ulonglong2*>(&sZW[s + 2]);
            ulonglong2 xy3 = *reinterpret_cast<const ulonglong2*>(&sXY[s + 3]);
            ulonglong2 zw3 = *reinterpret_cast<const ulonglong2*>(&sZW[s + 3]);

            EVAL_Q(Ax, Ay, Az, mA);
            EVAL_Q(Bx, By, Bz, mB);
            EVAL_Q(Cx, Cy, Cz, mC);
            EVAL_Q(Dx, Dy, Dz, mD);
        }
        const int ws = w * NSEG + seg;       // in [0, 32)
        gA = fmaxf(gA, key5(mA, ws));
        gB = fmaxf(gB, key5(mB, ws));
        gC = fmaxf(gC, key5(mC, ws));
        gD = fmaxf(gD, key5(mD, ws));
    }

    sKey[w * QPB + 4 * lane + 0] = gA;
    sKey[w * QPB + 4 * lane + 1] = gB;
    sKey[w * QPB + 4 * lane + 2] = gC;
    sKey[w * QPB + 4 * lane + 3] = gD;
    __syncthreads();

    // ── Pass 2: threads 0..127 = one query each; re-scan winning segment. ──
    float v0 = 0.0f, v1 = 0.0f, v2 = 0.0f, v3 = 0.0f;
    if (tid < QPB) {
        const int qq = blockIdx.x * QPB + tid;
        const float* pq = pred + ((size_t)bs * NPTS + qq) * 3;
        const float px = pq[0], py = pq[1], pz = pq[2];
        const ull qx2 = pack2(px), qy2 = pack2(py), qz2 = pack2(pz);

        float bestSeg = fmaxf(
            fmaxf(fmaxf(sKey[tid],           sKey[QPB + tid]),
                  fmaxf(sKey[2 * QPB + tid], sKey[3 * QPB + tid])),
            fmaxf(fmaxf(sKey[4 * QPB + tid], sKey[5 * QPB + tid]),
                  fmaxf(sKey[6 * QPB + tid], sKey[7 * QPB + tid])));
        const int wsWin    = __float_as_int(bestSeg) & 31;
        const int slotBase = wsWin * SEG_SLOTS;

        float kk = -1e30f;
        #pragma unroll 4
        for (int ii = 0; ii < SEG_SLOTS; ii++) {
            const int s = slotBase + ((ii + lane) & (SEG_SLOTS - 1));
            ulonglong2 xy = *reinterpret_cast<const ulonglong2*>(&sXY[s]);
            ulonglong2 zw = *reinterpret_cast<const ulonglong2*>(&sZW[s]);
            float u0, u1;
            score2(qx2, qy2, qz2, xy.x, xy.y, zw.x, zw.y, u0, u1);
            kk = fmax3(kk, key11(u0, 2 * s), key11(u1, 2 * s + 1));
        }
        const int bi   = __float_as_int(kk) & 2047;
        const int slot = bi >> 1;
        const bool odd = bi & 1;
        float4 xy = sXY[slot];
        float4 zw = sZW[slot];
        float tx = odd ? xy.y : xy.x;
        float ty = odd ? xy.w : xy.z;
        float tz = odd ? zw.y : zw.x;

        v0 = smooth_l1(px - tx) + smooth_l1(py - ty) + smooth_l1(pz - tz);
        v1 = px; v2 = py; v3 = pz;
    }

    // Block reduction over all 8 warps (warps 4-7 contribute zeros).
    #pragma unroll
    for (int o = 16; o > 0; o >>= 1) {
        v0 += __shfl_down_sync(0xFFFFFFFFu, v0, o);
        v1 += __shfl_down_sync(0xFFFFFFFFu, v1, o);
        v2 += __shfl_down_sync(0xFFFFFFFFu, v2, o);
        v3 += __shfl_down_sync(0xFFFFFFFFu, v3, o);
    }
    if (lane == 0) {
        sRed[0][w] = v0;
        sRed[1][w] = v1;
        sRed[2][w] = v2;
        sRed[3][w] = v3;
    }
    __syncthreads();
    if (tid == 0) {
        float t0 = 0, t1 = 0, t2 = 0, t3 = 0;
        #pragma unroll
        for (int k = 0; k < 4; k++) {     // only warps 0-3 are nonzero
            t0 += sRed[0][k]; t1 += sRed[1][k];
            t2 += sRed[2][k]; t3 += sRed[3][k];
        }
        const int bid = blockIdx.x + CHUNKS * (bs + BS_ * dir);
        g_part[bid] = t0 * W[bs] * (1.0f / (2.0f * (float)NPTS * 3.0f));
        g_cent[bid][0] = t1;
        g_cent[bid][1] = t2;
        g_cent[bid][2] = t3;
        __threadfence();
        sLast = (atomicAdd(&g_count, 1) == NBLK - 1);
    }
    __syncthreads();

    // ── Last block finalizes both outputs. ──
    if (sLast) {
        float s = 0.0f;
        for (int k = tid; k < NBLK; k += THREADS) s += g_part[k];

        float c = 0.0f;
        if (tid < 48) {
            const int b = tid / 3, d = tid % 3;
            float sx = 0.0f, st = 0.0f;
            #pragma unroll
            for (int ch = 0; ch < CHUNKS; ch++) {
                sx += g_cent[ch + CHUNKS * b][d];                 // dir 0 -> X
                st += g_cent[ch + CHUNKS * (b + BS_)][d];         // dir 1 -> T
            }
            c = smooth_l1((sx - st) * (1.0f / (float)NPTS));
        }

        #pragma unroll
        for (int o = 16; o > 0; o >>= 1) {
            s += __shfl_down_sync(0xFFFFFFFFu, s, o);
            c += __shfl_down_sync(0xFFFFFFFFu, c, o);
        }
        __shared__ float fRed[2][NWARP];
        if (lane == 0) { fRed[0][w] = s; fRed[1][w] = c; }
        __syncthreads();
        if (tid == 0) {
            float ts = 0, tc = 0;
            #pragma unroll
            for (int k = 0; k < NWARP; k++) { ts += fRed[0][k]; tc += fRed[1][k]; }
            out[0] = ts;
            out[1] = tc * (1.0f / 6.0f);   // / (B*3)
            g_count = 0;                   // self-reset for replay
        }
    }
}

extern "C" void kernel_launch(void* const* d_in, const int* in_sizes, int n_in,
                              void* d_out, int out_size) {
    const float* X = (const float*)d_in[0];   // [B,S,N,3]
    const float* T = (const float*)d_in[1];   // [B,S,N,3]
    const float* W = (const float*)d_in[2];   // [B,S]
    float* out = (float*)d_out;               // [2] -> (loss, lossc)

    dim3 grid(CHUNKS, BS_, 2);
    chamfer_kernel<<<grid, THREADS>>>(X, T, W, out);
}